// round 7
// baseline (speedup 1.0000x reference)
#include <cuda_runtime.h>
#include <math.h>

// DTW 2048x2048, out = sqrt(DTW[N-1][N-1]).
// v[i][j] = (x[i]-y[j])^2 + min(up,left,diag); border v[-1][-1]=0 else inf.
//
// Warp-autonomous systolic pipeline, single CTA, NO main-loop barrier:
//  - 128 threads = 4 warps, 1 per SMSP. Stage t = thread t owns cols
//    [16t,16t+16); rows stream in chunks of NR=4 (NK=512 chunks).
//  - intra-warp edges: __shfl_up_sync of previous iteration's vout.
//  - cross-warp edges (3 boundaries): 512-slot smem data+flag arrays,
//    producer lane31 predicated st.shared.v4 + st.release.cta flag;
//    consumer does a warp-uniform ld.acquire.cta poll. CTA scope only
//    (R4 lesson: cluster scope is ~10x costlier).
//  - each warp runs exactly 543 iterations (512 + 31 intra-warp skew);
//    fill/drain lanes use INF-propagating junk tiles (never stored).
// Per-cell arithmetic token-identical to R1/R5 -> bitwise-identical result.

#define NT    128
#define NW    4
#define NC    16
#define NR    4
#define LEN   2048
#define NK    (LEN / NR)    // 512
#define ITERS (NK + 31)     // 543

__global__ __launch_bounds__(NT, 1)
void dtw_kernel(const float* __restrict__ x,
                const float* __restrict__ y,
                float* __restrict__ out)
{
    __shared__ float    xs[LEN];             // 8 KB
    __shared__ float4   edata[NW - 1][NK];   // 24 KB cross-warp edge data
    __shared__ unsigned eflag[NW - 1][NK];   // 6 KB  ready flags

    const int tid  = threadIdx.x;
    const int lane = tid & 31;
    const int w    = tid >> 5;
    const float INF = __int_as_float(0x7f800000);

    for (int i = tid; i < LEN / 4; i += NT)
        reinterpret_cast<float4*>(xs)[i] = reinterpret_cast<const float4*>(x)[i];
    for (int i = tid; i < (NW - 1) * NK; i += NT)
        reinterpret_cast<unsigned*>(eflag)[i] = 0u;
    __syncthreads();   // only barrier: xs + flags visible

    // This thread's 16 y columns.
    float yc[NC];
    {
        const float4* y4 = reinterpret_cast<const float4*>(y + tid * NC);
        #pragma unroll
        for (int q = 0; q < NC / 4; q++) {
            float4 v = y4[q];
            yc[4*q+0] = v.x; yc[4*q+1] = v.y; yc[4*q+2] = v.z; yc[4*q+3] = v.w;
        }
    }

    float prev[NC];
    #pragma unroll
    for (int c = 0; c < NC; c++) prev[c] = INF;
    float  diag_edge = (tid == 0) ? 0.0f : INF;
    float4 vout = make_float4(INF, INF, INF, INF);

    // Shared addresses (32-bit) for this warp's consumer/producer role.
    const int cw = (w > 0) ? (w - 1) : 0;
    const unsigned cons_flag = (unsigned)__cvta_generic_to_shared(&eflag[cw][0]);
    const unsigned cons_data = (unsigned)__cvta_generic_to_shared(&edata[cw][0]);
    const int pw = (w < NW - 1) ? w : 0;
    const unsigned prod_flag = (unsigned)__cvta_generic_to_shared(&eflag[pw][0]);
    const unsigned prod_data = (unsigned)__cvta_generic_to_shared(&edata[pw][0]);
    const bool is_cons = (w > 0);
    const bool is_prod = (w < NW - 1);

    for (int it = 0; it < ITERS; it++) {
        // Intra-warp edges: lane l-1's previous-iteration vout.
        float4 e;
        e.x = __shfl_up_sync(0xffffffffu, vout.x, 1);
        e.y = __shfl_up_sync(0xffffffffu, vout.y, 1);
        e.z = __shfl_up_sync(0xffffffffu, vout.z, 1);
        e.w = __shfl_up_sync(0xffffffffu, vout.w, 1);

        // Lane 0's edge: poll the previous warp (chunk index == it);
        // INF for warp 0 (global left border) and during drain (it >= NK).
        float4 m = make_float4(INF, INF, INF, INF);
        if (is_cons && it < NK) {                 // warp-uniform branch
            const unsigned fa = cons_flag + ((unsigned)it << 2);
            unsigned f;
            do {
                asm volatile("ld.acquire.cta.shared.u32 %0, [%1];"
                             : "=r"(f) : "r"(fa) : "memory");
            } while (!f);
            const unsigned da = cons_data + ((unsigned)it << 4);
            asm volatile("ld.shared.v4.f32 {%0,%1,%2,%3}, [%4];"
                         : "=f"(m.x), "=f"(m.y), "=f"(m.z), "=f"(m.w)
                         : "r"(da) : "memory");
        }
        if (lane == 0) e = m;

        int k = it - lane;                  // this lane's chunk
        k = max(0, min(k, NK - 1));         // clamp: fill=INF-prop, drain junk
        const float4 xv = *reinterpret_cast<const float4*>(xs + (k << 2));
        const float xr[NR] = {xv.x, xv.y, xv.z, xv.w};
        const float er[NR] = {e.x, e.y, e.z, e.w};

        float left[NR], dgr[NR];
        left[0] = er[0]; left[1] = er[1]; left[2] = er[2]; left[3] = er[3];
        dgr[0]  = diag_edge; dgr[1] = er[0]; dgr[2] = er[1]; dgr[3] = er[2];
        diag_edge = er[NR - 1];

        // Stagger-1 intra-tile wavefront (4 concurrent dependency chains).
        #pragma unroll
        for (int jj = 0; jj < NC + NR - 1; jj++) {
            #pragma unroll
            for (int i = 0; i < NR; i++) {
                const int j = jj - i;       // compile-time after unroll
                if (j >= 0 && j < NC) {
                    float d  = xr[i] - yc[j];
                    float up = prev[j];
                    float mm = fminf(fminf(up, dgr[i]), left[i]);
                    float v  = fmaf(d, d, mm);
                    dgr[i]  = up;
                    prev[j] = v;
                    left[i] = v;
                }
            }
        }
        vout = make_float4(left[0], left[1], left[2], left[3]);

        // Producer push (lane 31, real chunks only): data, then release-flag.
        // Predicated stores (no BSSY/BSYNC divergence).
        const int kp = it - 31;
        const int pc = (is_prod && lane == 31 && kp >= 0 && kp < NK) ? 1 : 0;
        const unsigned da = prod_data + ((unsigned)kp << 4);
        const unsigned fa = prod_flag + ((unsigned)kp << 2);
        asm volatile("{ .reg .pred p; setp.ne.s32 p, %5, 0;\n\t"
                     "@p st.shared.v4.f32 [%0], {%1,%2,%3,%4}; }"
                     :: "r"(da), "f"(vout.x), "f"(vout.y), "f"(vout.z),
                        "f"(vout.w), "r"(pc) : "memory");
        asm volatile("{ .reg .pred p; setp.ne.s32 p, %1, 0;\n\t"
                     "@p st.release.cta.shared.u32 [%0], 1; }"
                     :: "r"(fa), "r"(pc) : "memory");
    }

    // Thread 127, iteration 542: chunk 511 -> vout.w = v[2047][2047].
    if (tid == NT - 1) out[0] = sqrtf(vout.w);
}

extern "C" void kernel_launch(void* const* d_in, const int* in_sizes, int n_in,
                              void* d_out, int out_size)
{
    const float* x = (const float*)d_in[0];
    const float* y = (const float*)d_in[1];
    float* out = (float*)d_out;
    (void)in_sizes; (void)n_in; (void)out_size;
    dtw_kernel<<<1, NT>>>(x, y, out);
}

// round 8
// speedup vs baseline: 1.2691x; 1.2691x over previous
#include <cuda_runtime.h>
#include <math.h>

// DTW 2048x2048, out = sqrt(DTW[N-1][N-1]).
// v[i][j] = (x[i]-y[j])^2 + min(up,left,diag); border v[-1][-1]=0 else inf.
//
// Superstep systolic wavefront, single CTA, 128 threads (4 warps, 1/SMSP):
//  - stage t owns cols [16t,16t+16); rows in chunks of NR=4 (NK=512).
//  - intra-warp edges: __shfl_up_sync of previous sub-iteration's vout
//    (always the same-chunk edge of stage t-1; holds in fill/steady/drain).
//  - cross-warp edges: 16-slot parity double-buffer in smem; warp offset
//    OFF=47 makes producer-write -> consumer-read exactly one superstep
//    (16 sub-iters) apart; ONE __syncthreads per superstep orders both
//    visibility and reuse. No flags, no polling (R4/R6 lesson).
//  - sub-iter i: lane l of warp w works chunk k = i - l - 47w if 0<=k<512.
// Per-cell arithmetic token-identical to R1/R5 -> bitwise-identical result.

#define NT   128
#define NW   4
#define NC   16
#define NR   4
#define LEN  2048
#define NK   (LEN / NR)   // 512
#define NU   16           // sub-iters per superstep
#define OFF  (NU + 31)    // 47: inter-warp stage offset (in sub-iters)
#define MS   43           // supersteps: 43*16=688 >= 512+3*47+32 = 685

__global__ __launch_bounds__(NT, 1)
void dtw_kernel(const float* __restrict__ x,
                const float* __restrict__ y,
                float* __restrict__ out)
{
    __shared__ float  xs[LEN];                // 8 KB
    __shared__ float4 ebuf[NW - 1][2][NU];    // 1.5 KB cross-warp edges

    const int tid  = threadIdx.x;
    const int lane = tid & 31;
    const int w    = tid >> 5;
    const float INF = __int_as_float(0x7f800000);

    for (int i = tid; i < LEN / 4; i += NT)
        reinterpret_cast<float4*>(xs)[i] = reinterpret_cast<const float4*>(x)[i];

    float yc[NC];
    {
        const float4* y4 = reinterpret_cast<const float4*>(y + tid * NC);
        #pragma unroll
        for (int q = 0; q < NC / 4; q++) {
            float4 v = y4[q];
            yc[4*q+0] = v.x; yc[4*q+1] = v.y; yc[4*q+2] = v.z; yc[4*q+3] = v.w;
        }
    }

    float prev[NC];
    #pragma unroll
    for (int c = 0; c < NC; c++) prev[c] = INF;
    float  diag_edge = (tid == 0) ? 0.0f : INF;
    float4 vout = make_float4(INF, INF, INF, INF);

    const int  kofs    = lane + OFF * w;   // chunk = i - kofs
    const bool is_cons = (w > 0);
    const int  pc_warp = (w < NW - 1) ? 1 : 0;
    // Producer store target base (this warp's boundary buffer).
    const unsigned pbase = (unsigned)__cvta_generic_to_shared(
        &ebuf[(w < NW - 1) ? w : 0][0][0]);

    int i = 0;  // global sub-iteration counter
    for (int m = 0; m < MS; m++) {
        __syncthreads();
        const int rpar = (m + 1) & 1;   // consumer parity (written last superstep)
        const int wpar = m & 1;         // producer parity
        #pragma unroll 1
        for (int u = 0; u < NU; u++, i++) {
            // Intra-warp edge: lane l-1's previous sub-iter vout (same chunk).
            float4 e;
            e.x = __shfl_up_sync(0xffffffffu, vout.x, 1);
            e.y = __shfl_up_sync(0xffffffffu, vout.y, 1);
            e.z = __shfl_up_sync(0xffffffffu, vout.z, 1);
            e.w = __shfl_up_sync(0xffffffffu, vout.w, 1);

            // Lane 0 edge: cross-warp buffer (warp-uniform address, broadcast),
            // INF for warp 0 (global border) and outside the valid window.
            float4 cm = make_float4(INF, INF, INF, INF);
            const int k0 = i - OFF * w;          // warp-uniform
            if (is_cons && (unsigned)k0 < (unsigned)NK)
                cm = ebuf[w - 1][rpar][k0 & (NU - 1)];
            if (lane == 0) e = cm;

            const int k = i - kofs;
            const int act = ((unsigned)k < (unsigned)NK) ? 1 : 0;
            if (act) {
                const float4 xv = *reinterpret_cast<const float4*>(xs + (k << 2));
                const float xr[NR] = {xv.x, xv.y, xv.z, xv.w};
                const float er[NR] = {e.x, e.y, e.z, e.w};

                float left[NR], dgr[NR];
                left[0] = er[0]; left[1] = er[1]; left[2] = er[2]; left[3] = er[3];
                dgr[0]  = diag_edge; dgr[1] = er[0]; dgr[2] = er[1]; dgr[3] = er[2];
                diag_edge = er[NR - 1];

                // Stagger-1 intra-tile wavefront (4 concurrent chains).
                #pragma unroll
                for (int jj = 0; jj < NC + NR - 1; jj++) {
                    #pragma unroll
                    for (int ii = 0; ii < NR; ii++) {
                        const int j = jj - ii;   // compile-time after unroll
                        if (j >= 0 && j < NC) {
                            float d  = xr[ii] - yc[j];
                            float up = prev[j];
                            float mm = fminf(fminf(up, dgr[ii]), left[ii]);
                            float v  = fmaf(d, d, mm);
                            dgr[ii] = up;
                            prev[j] = v;
                            left[ii]= v;
                        }
                    }
                }
                vout = make_float4(left[0], left[1], left[2], left[3]);
            }

            // Producer: lane 31, non-last warp, valid chunk -> predicated
            // STS.128 into slot [wpar][k & 15] (no divergence, no flag).
            const int pc = (lane == 31) ? (pc_warp & act) : 0;
            const unsigned da = pbase + (unsigned)((wpar * NU + (k & (NU - 1))) << 4);
            asm volatile("{ .reg .pred p; setp.ne.s32 p, %5, 0;\n\t"
                         "@p st.shared.v4.f32 [%0], {%1,%2,%3,%4}; }"
                         :: "r"(da), "f"(vout.x), "f"(vout.y), "f"(vout.z),
                            "f"(vout.w), "r"(pc) : "memory");
        }
    }

    // Thread 127 (warp 3, lane 31): chunk 511 done at i=683 -> vout.w = final.
    if (tid == NT - 1) out[0] = sqrtf(vout.w);
}

extern "C" void kernel_launch(void* const* d_in, const int* in_sizes, int n_in,
                              void* d_out, int out_size)
{
    const float* x = (const float*)d_in[0];
    const float* y = (const float*)d_in[1];
    float* out = (float*)d_out;
    (void)in_sizes; (void)n_in; (void)out_size;
    dtw_kernel<<<1, NT>>>(x, y, out);
}